// round 1
// baseline (speedup 1.0000x reference)
#include <cuda_runtime.h>

// ---------------- problem constants ----------------
#define BATCH     8
#define NTOK      4096
#define CCH       768
#define NHEAD     12
#define HDIM      64
#define NWIN      16      // windows per image
#define WTOK      256     // tokens per window
#define K_DIM     768
#define SCALE     0.125f

// scratch: qkv in layout [t][b][win][h][n][d], and y (attention out, original token order)
__device__ float g_qkv[3 * BATCH * NWIN * NHEAD * WTOK * HDIM];   // 75,497,472 floats
__device__ float g_y[BATCH * NTOK * CCH];                          // 25,165,824 floats

#define QKV_PLANE (BATCH * NWIN * NHEAD * WTOK * HDIM)             // 25,165,824

// permuted token p -> original token index
__device__ __forceinline__ int perm_tok(int p) {
    int wnd = p >> 8, r = p & 255;
    int wr = wnd >> 2, wc = wnd & 3;
    int i = r >> 4, j = r & 15;
    return ((wr << 4) + i) * 64 + (wc << 4) + j;
}

// ---------------- SGEMM: C[m][o] = sum_k A[m][k] * Bw[o][k]  (A row-major, Bw row-major = B^T) ----
// MODE 0: A = x with window-permuted rows; scatter-store into g_qkv layout.
// MODE 1: A = g_y; store Cout[m][o] = acc + bias[o].
template <int MODE>
__global__ __launch_bounds__(256, 2)
void gemm_kernel(const float* __restrict__ A, const float* __restrict__ Bw,
                 const float* __restrict__ bias, float* __restrict__ Cout)
{
    constexpr int BK = 16, BM = 128, LDSR = 132;
    __shared__ float As[BK * LDSR];
    __shared__ float Bs[BK * LDSR];

    const int tid = threadIdx.x;
    const int m0 = blockIdx.y * BM;
    const int n0 = blockIdx.x * 128;
    const int lr = tid >> 2;           // 0..63
    const int lc = (tid & 3) << 2;     // 0,4,8,12
    const int ty = tid >> 4;           // 0..15
    const int tx = tid & 15;           // 0..15

    const float* Aeff = (MODE == 0) ? A : (const float*)g_y;

    // per-thread global row pointers (two rows each for A and B tiles)
    const float *arow0, *arow1;
    {
        int m = m0 + lr, m2 = m + 64;
        if (MODE == 0) {
            int b = m >> 12, p = m & 4095;
            arow0 = Aeff + (size_t)((b << 12) + perm_tok(p)) * K_DIM;
            b = m2 >> 12; p = m2 & 4095;
            arow1 = Aeff + (size_t)((b << 12) + perm_tok(p)) * K_DIM;
        } else {
            arow0 = Aeff + (size_t)m * K_DIM;
            arow1 = Aeff + (size_t)m2 * K_DIM;
        }
    }
    const float* brow0 = Bw + (size_t)(n0 + lr) * K_DIM;
    const float* brow1 = Bw + (size_t)(n0 + lr + 64) * K_DIM;

    float acc[8][8];
#pragma unroll
    for (int i = 0; i < 8; i++)
#pragma unroll
        for (int j = 0; j < 8; j++) acc[i][j] = 0.f;

    for (int k0 = 0; k0 < K_DIM; k0 += BK) {
        float4 a0 = *(const float4*)(arow0 + k0 + lc);
        float4 a1 = *(const float4*)(arow1 + k0 + lc);
        float4 b0 = *(const float4*)(brow0 + k0 + lc);
        float4 b1 = *(const float4*)(brow1 + k0 + lc);

        As[(lc + 0) * LDSR + lr] = a0.x;
        As[(lc + 1) * LDSR + lr] = a0.y;
        As[(lc + 2) * LDSR + lr] = a0.z;
        As[(lc + 3) * LDSR + lr] = a0.w;
        As[(lc + 0) * LDSR + lr + 64] = a1.x;
        As[(lc + 1) * LDSR + lr + 64] = a1.y;
        As[(lc + 2) * LDSR + lr + 64] = a1.z;
        As[(lc + 3) * LDSR + lr + 64] = a1.w;

        Bs[(lc + 0) * LDSR + lr] = b0.x;
        Bs[(lc + 1) * LDSR + lr] = b0.y;
        Bs[(lc + 2) * LDSR + lr] = b0.z;
        Bs[(lc + 3) * LDSR + lr] = b0.w;
        Bs[(lc + 0) * LDSR + lr + 64] = b1.x;
        Bs[(lc + 1) * LDSR + lr + 64] = b1.y;
        Bs[(lc + 2) * LDSR + lr + 64] = b1.z;
        Bs[(lc + 3) * LDSR + lr + 64] = b1.w;

        __syncthreads();

#pragma unroll
        for (int kk = 0; kk < BK; kk++) {
            float4 av0 = *(const float4*)&As[kk * LDSR + ty * 8];
            float4 av1 = *(const float4*)&As[kk * LDSR + ty * 8 + 4];
            float4 bv0 = *(const float4*)&Bs[kk * LDSR + tx * 8];
            float4 bv1 = *(const float4*)&Bs[kk * LDSR + tx * 8 + 4];
            float av[8] = {av0.x, av0.y, av0.z, av0.w, av1.x, av1.y, av1.z, av1.w};
            float bv[8] = {bv0.x, bv0.y, bv0.z, bv0.w, bv1.x, bv1.y, bv1.z, bv1.w};
#pragma unroll
            for (int i = 0; i < 8; i++)
#pragma unroll
                for (int j = 0; j < 8; j++)
                    acc[i][j] += av[i] * bv[j];
        }
        __syncthreads();
    }

    if (MODE == 0) {
#pragma unroll
        for (int i = 0; i < 8; i++) {
            int m = m0 + ty * 8 + i;
            int b = m >> 12, p = m & 4095;
            int wnd = p >> 8, r = p & 255;
#pragma unroll
            for (int j = 0; j < 8; j++) {
                int o = n0 + tx * 8 + j;
                int t = o / CCH;
                int rem = o - t * CCH;
                int h = rem >> 6, d = rem & 63;
                size_t idx = ((((size_t)t * BATCH + b) * NWIN + wnd) * NHEAD + h);
                idx = (idx * WTOK + r) * HDIM + d;
                g_qkv[idx] = acc[i][j];
            }
        }
    } else {
#pragma unroll
        for (int i = 0; i < 8; i++) {
            int m = m0 + ty * 8 + i;
            float* crow = Cout + (size_t)m * CCH + n0 + tx * 8;
#pragma unroll
            for (int j = 0; j < 8; j++) {
                crow[j] = acc[i][j] + bias[n0 + tx * 8 + j];
            }
        }
    }
}

// ---------------- attention: one block per (b, window, head); 256 threads, one q-row per thread ---
__global__ __launch_bounds__(256, 1)
void attn_kernel()
{
    extern __shared__ float sm[];
    float* Qs = sm;            // 256*64
    float* Ks = sm + 16384;    // 256*64
    float* Vs = sm + 32768;    // 256*64

    const int tid = threadIdx.x;
    const int blk = blockIdx.x;
    const int h = blk % NHEAD;
    const int t2 = blk / NHEAD;
    const int wnd = t2 % NWIN;
    const int b = t2 / NWIN;

    const size_t base = ((((size_t)b * NWIN + wnd) * NHEAD + h) * WTOK) * HDIM;
    const float* Qg = g_qkv + base;
    const float* Kg = g_qkv + (size_t)QKV_PLANE + base;
    const float* Vg = g_qkv + 2 * (size_t)QKV_PLANE + base;

    // cooperative load: 16384 floats per tensor = 4096 float4, 16 per thread
#pragma unroll 4
    for (int idx = tid; idx < 4096; idx += 256) {
        ((float4*)Qs)[idx] = ((const float4*)Qg)[idx];
        ((float4*)Ks)[idx] = ((const float4*)Kg)[idx];
        ((float4*)Vs)[idx] = ((const float4*)Vg)[idx];
    }
    __syncthreads();

    // this thread's q row -> registers
    float q[64];
    {
        const float4* qr = (const float4*)(Qs + tid * 64);
#pragma unroll
        for (int d4 = 0; d4 < 16; d4++) {
            float4 v = qr[d4];
            q[d4 * 4 + 0] = v.x; q[d4 * 4 + 1] = v.y;
            q[d4 * 4 + 2] = v.z; q[d4 * 4 + 3] = v.w;
        }
    }

    float acc[64];
#pragma unroll
    for (int d = 0; d < 64; d++) acc[d] = 0.f;
    float mrun = -1e30f, lrun = 0.f;

    for (int jt = 0; jt < WTOK; jt += 16) {
        float s[16];
#pragma unroll
        for (int jj = 0; jj < 16; jj++) {
            const float4* kr = (const float4*)(Ks + (jt + jj) * 64);
            float sum = 0.f;
#pragma unroll
            for (int d4 = 0; d4 < 16; d4++) {
                float4 kv = kr[d4];
                sum += q[d4 * 4 + 0] * kv.x + q[d4 * 4 + 1] * kv.y
                     + q[d4 * 4 + 2] * kv.z + q[d4 * 4 + 3] * kv.w;
            }
            s[jj] = sum * SCALE;
        }

        float mnew = mrun;
#pragma unroll
        for (int jj = 0; jj < 16; jj++) mnew = fmaxf(mnew, s[jj]);

        float corr = __expf(mrun - mnew);
        lrun *= corr;
#pragma unroll
        for (int d = 0; d < 64; d++) acc[d] *= corr;

#pragma unroll
        for (int jj = 0; jj < 16; jj++) {
            float p = __expf(s[jj] - mnew);
            lrun += p;
            const float4* vr = (const float4*)(Vs + (jt + jj) * 64);
#pragma unroll
            for (int d4 = 0; d4 < 16; d4++) {
                float4 vv = vr[d4];
                acc[d4 * 4 + 0] += p * vv.x;
                acc[d4 * 4 + 1] += p * vv.y;
                acc[d4 * 4 + 2] += p * vv.z;
                acc[d4 * 4 + 3] += p * vv.w;
            }
        }
        mrun = mnew;
    }

    float inv = 1.f / lrun;
    int n = perm_tok(wnd * WTOK + tid);   // original token position (inverse perm)
    float* yout = g_y + ((size_t)(b * NTOK + n)) * CCH + h * HDIM;
#pragma unroll
    for (int d4 = 0; d4 < 16; d4++) {
        float4 o;
        o.x = acc[d4 * 4 + 0] * inv;
        o.y = acc[d4 * 4 + 1] * inv;
        o.z = acc[d4 * 4 + 2] * inv;
        o.w = acc[d4 * 4 + 3] * inv;
        ((float4*)yout)[d4] = o;
    }
}

// ---------------- launch ----------------
extern "C" void kernel_launch(void* const* d_in, const int* in_sizes, int n_in,
                              void* d_out, int out_size)
{
    const float* x      = (const float*)d_in[0];
    const float* qkv_w  = (const float*)d_in[1];
    const float* proj_w = (const float*)d_in[2];
    const float* proj_b = (const float*)d_in[3];
    float* out = (float*)d_out;

    cudaFuncSetAttribute(attn_kernel, cudaFuncAttributeMaxDynamicSharedMemorySize, 196608);

    // QKV: M=32768, N=2304 -> grid (18, 256)
    dim3 gq(2304 / 128, 32768 / 128);
    gemm_kernel<0><<<gq, 256>>>(x, qkv_w, nullptr, nullptr);

    // attention: 8*16*12 = 1536 blocks
    attn_kernel<<<BATCH * NWIN * NHEAD, 256, 196608>>>();

    // proj: M=32768, N=768 -> grid (6, 256)
    dim3 gp(768 / 128, 32768 / 128);
    gemm_kernel<1><<<gp, 256>>>(nullptr, proj_w, proj_b, out);
}

// round 2
// speedup vs baseline: 1.7308x; 1.7308x over previous
#include <cuda_runtime.h>

// ---------------- problem constants ----------------
#define BATCH     8
#define NTOK      4096
#define CCH       768
#define NHEAD     12
#define HDIM      64
#define NWIN      16      // windows per image
#define WTOK      256     // tokens per window
#define K_DIM     768
#define SCALE     0.125f

typedef unsigned long long ull;

// scratch: qkv in layout [t][b][win][h][n][d], and y (attention out, original token order)
__device__ float g_qkv[3 * BATCH * NWIN * NHEAD * WTOK * HDIM];
__device__ float g_y[BATCH * NTOK * CCH];

#define QKV_PLANE (BATCH * NWIN * NHEAD * WTOK * HDIM)

// ---------------- packed f32x2 helpers ----------------
__device__ __forceinline__ void ffma2(ull& c, ull a, ull b) {
    asm("fma.rn.f32x2 %0, %1, %2, %0;" : "+l"(c) : "l"(a), "l"(b));
}
__device__ __forceinline__ void fmul2(ull& c, ull a) {
    asm("mul.rn.f32x2 %0, %0, %1;" : "+l"(c) : "l"(a));
}
__device__ __forceinline__ ull pack2(float x, float y) {
    ull r;
    asm("mov.b64 %0, {%1, %2};" : "=l"(r) : "f"(x), "f"(y));
    return r;
}
__device__ __forceinline__ float2 unpack2(ull v) {
    float2 f;
    asm("mov.b64 {%0, %1}, %2;" : "=f"(f.x), "=f"(f.y) : "l"(v));
    return f;
}

// permuted token p -> original token index
__device__ __forceinline__ int perm_tok(int p) {
    int wnd = p >> 8, r = p & 255;
    int wr = wnd >> 2, wc = wnd & 3;
    int i = r >> 4, j = r & 15;
    return ((wr << 4) + i) * 64 + (wc << 4) + j;
}

// ---------------- SGEMM: C[m][o] = sum_k A[m][k] * Bw[o][k] ----------------
// MODE 0: A = x with window-permuted rows; scatter-store into g_qkv layout.
// MODE 1: A = g_y; store Cout[m][o] = acc + bias[o].
template <int MODE>
__global__ __launch_bounds__(256, 2)
void gemm_kernel(const float* __restrict__ A, const float* __restrict__ Bw,
                 const float* __restrict__ bias, float* __restrict__ Cout)
{
    constexpr int BK = 16, BM = 128, LDSR = 132;
    __shared__ float As[BK * LDSR];
    __shared__ float Bs[BK * LDSR];

    const int tid = threadIdx.x;
    const int m0 = blockIdx.y * BM;
    const int n0 = blockIdx.x * 128;
    const int lr = tid >> 2;           // 0..63
    const int lc = (tid & 3) << 2;     // 0,4,8,12
    const int ty = tid >> 4;           // 0..15
    const int tx = tid & 15;           // 0..15

    const float* Aeff = (MODE == 0) ? A : (const float*)g_y;

    const float *arow0, *arow1;
    {
        int m = m0 + lr, m2 = m + 64;
        if (MODE == 0) {
            int b = m >> 12, p = m & 4095;
            arow0 = Aeff + (size_t)((b << 12) + perm_tok(p)) * K_DIM;
            b = m2 >> 12; p = m2 & 4095;
            arow1 = Aeff + (size_t)((b << 12) + perm_tok(p)) * K_DIM;
        } else {
            arow0 = Aeff + (size_t)m * K_DIM;
            arow1 = Aeff + (size_t)m2 * K_DIM;
        }
    }
    const float* brow0 = Bw + (size_t)(n0 + lr) * K_DIM;
    const float* brow1 = Bw + (size_t)(n0 + lr + 64) * K_DIM;

    ull acc2[8][4];
#pragma unroll
    for (int i = 0; i < 8; i++)
#pragma unroll
        for (int j = 0; j < 4; j++) acc2[i][j] = 0ull;

    for (int k0 = 0; k0 < K_DIM; k0 += BK) {
        float4 a0 = *(const float4*)(arow0 + k0 + lc);
        float4 a1 = *(const float4*)(arow1 + k0 + lc);
        float4 b0 = *(const float4*)(brow0 + k0 + lc);
        float4 b1 = *(const float4*)(brow1 + k0 + lc);

        As[(lc + 0) * LDSR + lr] = a0.x;
        As[(lc + 1) * LDSR + lr] = a0.y;
        As[(lc + 2) * LDSR + lr] = a0.z;
        As[(lc + 3) * LDSR + lr] = a0.w;
        As[(lc + 0) * LDSR + lr + 64] = a1.x;
        As[(lc + 1) * LDSR + lr + 64] = a1.y;
        As[(lc + 2) * LDSR + lr + 64] = a1.z;
        As[(lc + 3) * LDSR + lr + 64] = a1.w;

        Bs[(lc + 0) * LDSR + lr] = b0.x;
        Bs[(lc + 1) * LDSR + lr] = b0.y;
        Bs[(lc + 2) * LDSR + lr] = b0.z;
        Bs[(lc + 3) * LDSR + lr] = b0.w;
        Bs[(lc + 0) * LDSR + lr + 64] = b1.x;
        Bs[(lc + 1) * LDSR + lr + 64] = b1.y;
        Bs[(lc + 2) * LDSR + lr + 64] = b1.z;
        Bs[(lc + 3) * LDSR + lr + 64] = b1.w;

        __syncthreads();

#pragma unroll
        for (int kk = 0; kk < BK; kk++) {
            float4 av0 = *(const float4*)&As[kk * LDSR + ty * 8];
            float4 av1 = *(const float4*)&As[kk * LDSR + ty * 8 + 4];
            float4 bv0 = *(const float4*)&Bs[kk * LDSR + tx * 8];
            float4 bv1 = *(const float4*)&Bs[kk * LDSR + tx * 8 + 4];

            ull bq[4];
            bq[0] = pack2(bv0.x, bv0.y);
            bq[1] = pack2(bv0.z, bv0.w);
            bq[2] = pack2(bv1.x, bv1.y);
            bq[3] = pack2(bv1.z, bv1.w);

            ull ad[8];
            ad[0] = pack2(av0.x, av0.x);
            ad[1] = pack2(av0.y, av0.y);
            ad[2] = pack2(av0.z, av0.z);
            ad[3] = pack2(av0.w, av0.w);
            ad[4] = pack2(av1.x, av1.x);
            ad[5] = pack2(av1.y, av1.y);
            ad[6] = pack2(av1.z, av1.z);
            ad[7] = pack2(av1.w, av1.w);

#pragma unroll
            for (int i = 0; i < 8; i++) {
                ffma2(acc2[i][0], ad[i], bq[0]);
                ffma2(acc2[i][1], ad[i], bq[1]);
                ffma2(acc2[i][2], ad[i], bq[2]);
                ffma2(acc2[i][3], ad[i], bq[3]);
            }
        }
        __syncthreads();
    }

    // unpack accumulator
    float acc[8][8];
#pragma unroll
    for (int i = 0; i < 8; i++)
#pragma unroll
        for (int j2 = 0; j2 < 4; j2++) {
            float2 u = unpack2(acc2[i][j2]);
            acc[i][2 * j2] = u.x;
            acc[i][2 * j2 + 1] = u.y;
        }

    if (MODE == 0) {
        // output column range n0+tx*8 .. +7 lies within one (t,h) pair:
        // 128-wide tiles never straddle a 768 boundary, and 8-aligned runs never
        // straddle a 64 boundary.
        const int t = n0 / CCH;
        const int rem0 = n0 - t * CCH + tx * 8;
        const int h = rem0 >> 6;
        const int d0 = rem0 & 63;
#pragma unroll
        for (int i = 0; i < 8; i++) {
            int m = m0 + ty * 8 + i;
            int b = m >> 12, p = m & 4095;
            int wnd = p >> 8, r = p & 255;
            size_t idx = ((((size_t)t * BATCH + b) * NWIN + wnd) * NHEAD + h);
            idx = (idx * WTOK + r) * HDIM + d0;
            float4* dst = (float4*)&g_qkv[idx];
            dst[0] = make_float4(acc[i][0], acc[i][1], acc[i][2], acc[i][3]);
            dst[1] = make_float4(acc[i][4], acc[i][5], acc[i][6], acc[i][7]);
        }
    } else {
        float4 bb0 = *(const float4*)&bias[n0 + tx * 8];
        float4 bb1 = *(const float4*)&bias[n0 + tx * 8 + 4];
#pragma unroll
        for (int i = 0; i < 8; i++) {
            int m = m0 + ty * 8 + i;
            float4* crow = (float4*)(Cout + (size_t)m * CCH + n0 + tx * 8);
            crow[0] = make_float4(acc[i][0] + bb0.x, acc[i][1] + bb0.y,
                                  acc[i][2] + bb0.z, acc[i][3] + bb0.w);
            crow[1] = make_float4(acc[i][4] + bb1.x, acc[i][5] + bb1.y,
                                  acc[i][6] + bb1.z, acc[i][7] + bb1.w);
        }
    }
}

// ---------------- attention: one block per (b, window, head) ----------------
__global__ __launch_bounds__(256, 1)
void attn_kernel()
{
    extern __shared__ float sm[];
    float* Qs = sm;            // 256*64
    float* Ks = sm + 16384;    // 256*64
    float* Vs = sm + 32768;    // 256*64

    const int tid = threadIdx.x;
    const int blk = blockIdx.x;
    const int h = blk % NHEAD;
    const int t2 = blk / NHEAD;
    const int wnd = t2 % NWIN;
    const int b = t2 / NWIN;

    const size_t base = ((((size_t)b * NWIN + wnd) * NHEAD + h) * WTOK) * HDIM;
    const float* Qg = g_qkv + base;
    const float* Kg = g_qkv + (size_t)QKV_PLANE + base;
    const float* Vg = g_qkv + 2 * (size_t)QKV_PLANE + base;

#pragma unroll 4
    for (int idx = tid; idx < 4096; idx += 256) {
        ((float4*)Qs)[idx] = ((const float4*)Qg)[idx];
        ((float4*)Ks)[idx] = ((const float4*)Kg)[idx];
        ((float4*)Vs)[idx] = ((const float4*)Vg)[idx];
    }
    __syncthreads();

    // this thread's q row as 32 packed pairs
    ull q2[32];
    {
        const ull* qp = (const ull*)(Qs + tid * 64);
#pragma unroll
        for (int i = 0; i < 32; i++) q2[i] = qp[i];
    }

    ull acc2[32];
#pragma unroll
    for (int i = 0; i < 32; i++) acc2[i] = 0ull;
    float mrun = -1e30f, lrun = 0.f;

    for (int jt = 0; jt < WTOK; jt += 16) {
        float s[16];
#pragma unroll
        for (int jj = 0; jj < 16; jj++) {
            const ull* kr = (const ull*)(Ks + (jt + jj) * 64);
            ull s2 = 0ull;
#pragma unroll
            for (int i = 0; i < 32; i++) ffma2(s2, q2[i], kr[i]);
            float2 sf = unpack2(s2);
            s[jj] = (sf.x + sf.y) * SCALE;
        }

        float mnew = mrun;
#pragma unroll
        for (int jj = 0; jj < 16; jj++) mnew = fmaxf(mnew, s[jj]);

        float corr = __expf(mrun - mnew);
        lrun *= corr;
        ull c2 = pack2(corr, corr);
#pragma unroll
        for (int i = 0; i < 32; i++) fmul2(acc2[i], c2);

#pragma unroll
        for (int jj = 0; jj < 16; jj++) {
            float p = __expf(s[jj] - mnew);
            lrun += p;
            ull p2 = pack2(p, p);
            const ull* vr = (const ull*)(Vs + (jt + jj) * 64);
#pragma unroll
            for (int i = 0; i < 32; i++) ffma2(acc2[i], p2, vr[i]);
        }
        mrun = mnew;
    }

    float inv = 1.f / lrun;
    int n = perm_tok(wnd * WTOK + tid);   // original token position (inverse perm)
    float* yout = g_y + ((size_t)(b * NTOK + n)) * CCH + h * HDIM;
#pragma unroll
    for (int i = 0; i < 16; i++) {
        float2 a = unpack2(acc2[2 * i]);
        float2 c = unpack2(acc2[2 * i + 1]);
        ((float4*)yout)[i] = make_float4(a.x * inv, a.y * inv, c.x * inv, c.y * inv);
    }
}

// ---------------- launch ----------------
extern "C" void kernel_launch(void* const* d_in, const int* in_sizes, int n_in,
                              void* d_out, int out_size)
{
    const float* x      = (const float*)d_in[0];
    const float* qkv_w  = (const float*)d_in[1];
    const float* proj_w = (const float*)d_in[2];
    const float* proj_b = (const float*)d_in[3];
    float* out = (float*)d_out;

    cudaFuncSetAttribute(attn_kernel, cudaFuncAttributeMaxDynamicSharedMemorySize, 196608);

    dim3 gq(2304 / 128, 32768 / 128);
    gemm_kernel<0><<<gq, 256>>>(x, qkv_w, nullptr, nullptr);

    attn_kernel<<<BATCH * NWIN * NHEAD, 256, 196608>>>();

    dim3 gp(768 / 128, 32768 / 128);
    gemm_kernel<1><<<gp, 256>>>(nullptr, proj_w, proj_b, out);
}

// round 7
// speedup vs baseline: 2.9580x; 1.7091x over previous
#include <cuda_runtime.h>
#include <cuda_bf16.h>

// ---------------- problem constants ----------------
#define BATCH 8
#define NTOK  4096
#define CCH   768
#define NHEAD 12
#define HDIM  64
#define NWIN  16
#define WTOK  256
#define K_DIM 768
#define SCALE 0.125f
#define MTOT  (BATCH * NTOK)     // 32768

typedef unsigned long long ull;
typedef unsigned int u32;

// ---------------- device scratch ----------------
__device__ float g_qkv[3u * BATCH * NWIN * NHEAD * WTOK * HDIM];   // fp32 QKV, [t][b][w][h][r][d]
__device__ __nv_bfloat16 g_xh[(size_t)MTOT * K_DIM];               // permuted x, hi
__device__ __nv_bfloat16 g_xl[(size_t)MTOT * K_DIM];               // permuted x, lo
__device__ __nv_bfloat16 g_yh[(size_t)MTOT * K_DIM];               // attn out (orig order), hi
__device__ __nv_bfloat16 g_yl[(size_t)MTOT * K_DIM];
__device__ __nv_bfloat16 g_wqh[2304 * 768], g_wql[2304 * 768];
__device__ __nv_bfloat16 g_wph[768 * 768],  g_wpl[768 * 768];

#define QKV_PLANE (BATCH * NWIN * NHEAD * WTOK * HDIM)

// ---------------- helpers ----------------
__device__ __forceinline__ void ffma2(ull& c, ull a, ull b) {
    asm("fma.rn.f32x2 %0, %1, %2, %0;" : "+l"(c) : "l"(a), "l"(b));
}
__device__ __forceinline__ void fmul2(ull& c, ull a) {
    asm("mul.rn.f32x2 %0, %0, %1;" : "+l"(c) : "l"(a));
}
__device__ __forceinline__ ull pack2(float x, float y) {
    ull r; asm("mov.b64 %0, {%1, %2};" : "=l"(r) : "f"(x), "f"(y)); return r;
}
__device__ __forceinline__ float2 unpack2(ull v) {
    float2 f; asm("mov.b64 {%0, %1}, %2;" : "=f"(f.x), "=f"(f.y) : "l"(v)); return f;
}
__device__ __forceinline__ int perm_tok(int p) {
    int wnd = p >> 8, r = p & 255;
    int wr = wnd >> 2, wc = wnd & 3;
    int i = r >> 4, j = r & 15;
    return ((wr << 4) + i) * 64 + (wc << 4) + j;
}
__device__ __forceinline__ u32 smem_u32(const void* p) {
    u32 a;
    asm("{ .reg .u64 t; cvta.to.shared.u64 t, %1; cvt.u32.u64 %0, t; }" : "=r"(a) : "l"(p));
    return a;
}
__device__ __forceinline__ void ldsm4(u32& r0, u32& r1, u32& r2, u32& r3, u32 addr) {
    asm volatile("ldmatrix.sync.aligned.m8n8.x4.shared.b16 {%0,%1,%2,%3}, [%4];"
                 : "=r"(r0), "=r"(r1), "=r"(r2), "=r"(r3) : "r"(addr));
}
__device__ __forceinline__ void mma16816(float* c, const u32* a, const u32* b) {
    asm volatile("mma.sync.aligned.m16n8k16.row.col.f32.bf16.bf16.f32 "
                 "{%0,%1,%2,%3}, {%4,%5,%6,%7}, {%8,%9}, {%0,%1,%2,%3};"
                 : "+f"(c[0]), "+f"(c[1]), "+f"(c[2]), "+f"(c[3])
                 : "r"(a[0]), "r"(a[1]), "r"(a[2]), "r"(a[3]), "r"(b[0]), "r"(b[1]));
}
__device__ __forceinline__ void cpasync16(u32 saddr, const void* g) {
    asm volatile("cp.async.cg.shared.global [%0], [%1], 16;" :: "r"(saddr), "l"(g) : "memory");
}
#define CP_COMMIT()  asm volatile("cp.async.commit_group;" ::: "memory")
#define CP_WAIT(n)   asm volatile("cp.async.wait_group %0;" :: "n"(n) : "memory")

// ---------------- convert kernels ----------------
__global__ __launch_bounds__(192) void convert_x(const float* __restrict__ x)
{
    const int m = blockIdx.x;
    const int t = threadIdx.x;
    const int b = m >> 12, p = m & 4095;
    const float4* src = (const float4*)(x + (size_t)((b << 12) + perm_tok(p)) * K_DIM);
    float4 v = src[t];
    __nv_bfloat16 h0 = __float2bfloat16(v.x), h1 = __float2bfloat16(v.y);
    __nv_bfloat16 h2 = __float2bfloat16(v.z), h3 = __float2bfloat16(v.w);
    __nv_bfloat162* dh = (__nv_bfloat162*)(g_xh + (size_t)m * K_DIM);
    __nv_bfloat162* dl = (__nv_bfloat162*)(g_xl + (size_t)m * K_DIM);
    __nv_bfloat162 a; a.x = h0; a.y = h1; dh[t * 2] = a;
    a.x = h2; a.y = h3; dh[t * 2 + 1] = a;
    a.x = __float2bfloat16(v.x - __bfloat162float(h0));
    a.y = __float2bfloat16(v.y - __bfloat162float(h1));
    dl[t * 2] = a;
    a.x = __float2bfloat16(v.z - __bfloat162float(h2));
    a.y = __float2bfloat16(v.w - __bfloat162float(h3));
    dl[t * 2 + 1] = a;
}

__global__ __launch_bounds__(192) void convert_w(const float* __restrict__ qkv_w,
                                                 const float* __restrict__ proj_w)
{
    const int row = blockIdx.x;
    const int t = threadIdx.x;
    const float* src;
    __nv_bfloat16 *dh, *dl;
    if (row < 2304) {
        src = qkv_w + (size_t)row * 768;
        dh = g_wqh + (size_t)row * 768; dl = g_wql + (size_t)row * 768;
    } else {
        int r2 = row - 2304;
        src = proj_w + (size_t)r2 * 768;
        dh = g_wph + (size_t)r2 * 768; dl = g_wpl + (size_t)r2 * 768;
    }
    float4 v = ((const float4*)src)[t];
    __nv_bfloat16 h0 = __float2bfloat16(v.x), h1 = __float2bfloat16(v.y);
    __nv_bfloat16 h2 = __float2bfloat16(v.z), h3 = __float2bfloat16(v.w);
    __nv_bfloat162 a;
    a.x = h0; a.y = h1; ((__nv_bfloat162*)dh)[t * 2] = a;
    a.x = h2; a.y = h3; ((__nv_bfloat162*)dh)[t * 2 + 1] = a;
    a.x = __float2bfloat16(v.x - __bfloat162float(h0));
    a.y = __float2bfloat16(v.y - __bfloat162float(h1));
    ((__nv_bfloat162*)dl)[t * 2] = a;
    a.x = __float2bfloat16(v.z - __bfloat162float(h2));
    a.y = __float2bfloat16(v.w - __bfloat162float(h3));
    ((__nv_bfloat162*)dl)[t * 2 + 1] = a;
}

// ---------------- mma.sync bf16 3-term-split GEMM ----------------
// C[m][n] = sum_k A[m][k]*W[n][k];  C = Ah*Wh + Ah*Wl + Al*Wh  (fp32 accum)
// CTA tile 128x128, BK=32, 8 warps (4x2), warp tile 32x64, double-buffered cp.async.
// smem per buffer: Ah|Al|Wh|Wl, each 128 rows x 40 halves (80B stride) = 10240B -> 40960B/buf.
#define GM_SMEM 81920

template <int MODE>
__global__ __launch_bounds__(256, 1)
void gemm_mma(const float* __restrict__ bias, float* __restrict__ Cout)
{
    extern __shared__ char smem[];
    const __nv_bfloat16* Abase_h = (MODE == 0) ? g_xh : g_yh;
    const __nv_bfloat16* Abase_l = (MODE == 0) ? g_xl : g_yl;
    const __nv_bfloat16* Wbase_h = (MODE == 0) ? g_wqh : g_wph;
    const __nv_bfloat16* Wbase_l = (MODE == 0) ? g_wql : g_wpl;

    const int tid = threadIdx.x;
    const int lane = tid & 31, wid = tid >> 5;
    const int wy = wid >> 1, wx = wid & 1;          // warp grid 4x2
    const int m0 = blockIdx.y * 128;
    const int n0 = blockIdx.x * 128;
    const u32 sb = smem_u32(smem);

    const __nv_bfloat16* Ahp = Abase_h + (size_t)m0 * 768;
    const __nv_bfloat16* Alp = Abase_l + (size_t)m0 * 768;
    const __nv_bfloat16* Whp = Wbase_h + (size_t)n0 * 768;
    const __nv_bfloat16* Wlp = Wbase_l + (size_t)n0 * 768;

    float acc[2][8][4];
#pragma unroll
    for (int mt = 0; mt < 2; mt++)
#pragma unroll
        for (int nt = 0; nt < 8; nt++)
#pragma unroll
            for (int j = 0; j < 4; j++) acc[mt][nt][j] = 0.f;

    // ldsm per-lane byte offsets within a tile region (before kstep offset)
    const u32 aOff = (u32)((wy * 32 + (lane & 15)) * 80 + ((lane >> 4) * 16));
    const u32 bOff = (u32)((wx * 64 + ((lane >> 4) << 3) + (lane & 7)) * 80
                           + (((lane >> 3) & 1) * 16));

    // --- tile loader: 8 cp.async x 16B per thread ---
    const int s0 = tid, row0 = s0 >> 2, q0 = s0 & 3;
    const int s1 = tid + 256, row1 = s1 >> 2, q1 = s1 & 3;

#define LOAD_TILE(c, buf) do {                                                    \
    u32 dbase = sb + (u32)(buf) * 40960u;                                         \
    int kk = (c) * 32;                                                            \
    cpasync16(dbase +         (u32)(row0 * 80 + q0 * 16), Ahp + (size_t)row0 * 768 + kk + q0 * 8); \
    cpasync16(dbase +         (u32)(row1 * 80 + q1 * 16), Ahp + (size_t)row1 * 768 + kk + q1 * 8); \
    cpasync16(dbase + 10240 + (u32)(row0 * 80 + q0 * 16), Alp + (size_t)row0 * 768 + kk + q0 * 8); \
    cpasync16(dbase + 10240 + (u32)(row1 * 80 + q1 * 16), Alp + (size_t)row1 * 768 + kk + q1 * 8); \
    cpasync16(dbase + 20480 + (u32)(row0 * 80 + q0 * 16), Whp + (size_t)row0 * 768 + kk + q0 * 8); \
    cpasync16(dbase + 20480 + (u32)(row1 * 80 + q1 * 16), Whp + (size_t)row1 * 768 + kk + q1 * 8); \
    cpasync16(dbase + 30720 + (u32)(row0 * 80 + q0 * 16), Wlp + (size_t)row0 * 768 + kk + q0 * 8); \
    cpasync16(dbase + 30720 + (u32)(row1 * 80 + q1 * 16), Wlp + (size_t)row1 * 768 + kk + q1 * 8); \
} while (0)

    LOAD_TILE(0, 0);
    CP_COMMIT();

    for (int c = 0; c < 24; c++) {
        const int buf = c & 1;
        if (c + 1 < 24) {
            LOAD_TILE(c + 1, buf ^ 1);
            CP_COMMIT();
            CP_WAIT(1);
        } else {
            CP_WAIT(0);
        }
        __syncthreads();

        const u32 base = sb + (u32)buf * 40960u;
#pragma unroll
        for (int ks = 0; ks < 2; ks++) {
            const u32 kb = (u32)(ks * 32);          // 16 halves
            u32 ah[2][4], al[2][4], bh[8][2], bl[8][2];
#pragma unroll
            for (int mt = 0; mt < 2; mt++) {
                u32 ad = base + aOff + (u32)(mt * 16 * 80) + kb;
                ldsm4(ah[mt][0], ah[mt][1], ah[mt][2], ah[mt][3], ad);
                ldsm4(al[mt][0], al[mt][1], al[mt][2], al[mt][3], ad + 10240);
            }
#pragma unroll
            for (int p = 0; p < 4; p++) {
                u32 bd = base + 20480 + bOff + (u32)(p * 16 * 80) + kb;
                u32 r0, r1, r2, r3;
                ldsm4(r0, r1, r2, r3, bd);
                bh[2 * p][0] = r0; bh[2 * p][1] = r1;
                bh[2 * p + 1][0] = r2; bh[2 * p + 1][1] = r3;
                ldsm4(r0, r1, r2, r3, bd + 10240);
                bl[2 * p][0] = r0; bl[2 * p][1] = r1;
                bl[2 * p + 1][0] = r2; bl[2 * p + 1][1] = r3;
            }
#pragma unroll
            for (int mt = 0; mt < 2; mt++)
#pragma unroll
                for (int nt = 0; nt < 8; nt++) {
                    mma16816(acc[mt][nt], ah[mt], bh[nt]);
                    mma16816(acc[mt][nt], ah[mt], bl[nt]);
                    mma16816(acc[mt][nt], al[mt], bh[nt]);
                }
        }
        __syncthreads();
    }

    // ---- epilogue ----
#pragma unroll
    for (int mt = 0; mt < 2; mt++) {
        const int m_g = m0 + wy * 32 + mt * 16 + (lane >> 2);
        if (MODE == 0) {
            const int bq = m_g >> 12, ptok = m_g & 4095;
            const int wnd = ptok >> 8, rr = ptok & 255;
#pragma unroll
            for (int nt = 0; nt < 8; nt++) {
                const int ncol = n0 + wx * 64 + nt * 8;
                const int t = ncol / 768;
                const int rem = ncol - t * 768;
                const int h = rem >> 6;
                const int d = (rem & 63) + 2 * (lane & 3);
                size_t rowbase = ((((size_t)t * 8 + bq) * 16 + wnd) * 12 + h) * 256;
                *(float2*)(g_qkv + (rowbase + rr) * 64 + d) =
                    make_float2(acc[mt][nt][0], acc[mt][nt][1]);
                *(float2*)(g_qkv + (rowbase + rr + 8) * 64 + d) =
                    make_float2(acc[mt][nt][2], acc[mt][nt][3]);
            }
        } else {
#pragma unroll
            for (int nt = 0; nt < 8; nt++) {
                const int ncol = n0 + wx * 64 + nt * 8 + 2 * (lane & 3);
                const float b0 = bias[ncol], b1 = bias[ncol + 1];
                *(float2*)(Cout + (size_t)m_g * 768 + ncol) =
                    make_float2(acc[mt][nt][0] + b0, acc[mt][nt][1] + b1);
                *(float2*)(Cout + (size_t)(m_g + 8) * 768 + ncol) =
                    make_float2(acc[mt][nt][2] + b0, acc[mt][nt][3] + b1);
            }
        }
    }
#undef LOAD_TILE
}

// ---------------- attention: one block per (b, window, head); FFMA2; writes yh/yl bf16 ----
__global__ __launch_bounds__(256, 1)
void attn_kernel()
{
    extern __shared__ float sm[];
    float* Qs = sm;
    float* Ks = sm + 16384;
    float* Vs = sm + 32768;

    const int tid = threadIdx.x;
    const int blk = blockIdx.x;
    const int h = blk % NHEAD;
    const int t2 = blk / NHEAD;
    const int wnd = t2 % NWIN;
    const int b = t2 / NWIN;

    const size_t base = ((((size_t)b * NWIN + wnd) * NHEAD + h) * WTOK) * HDIM;
    const float* Qg = g_qkv + base;
    const float* Kg = g_qkv + (size_t)QKV_PLANE + base;
    const float* Vg = g_qkv + 2 * (size_t)QKV_PLANE + base;

#pragma unroll 4
    for (int idx = tid; idx < 4096; idx += 256) {
        ((float4*)Qs)[idx] = ((const float4*)Qg)[idx];
        ((float4*)Ks)[idx] = ((const float4*)Kg)[idx];
        ((float4*)Vs)[idx] = ((const float4*)Vg)[idx];
    }
    __syncthreads();

    ull q2[32];
    {
        const ull* qp = (const ull*)(Qs + tid * 64);
#pragma unroll
        for (int i = 0; i < 32; i++) q2[i] = qp[i];
    }

    ull acc2[32];
#pragma unroll
    for (int i = 0; i < 32; i++) acc2[i] = 0ull;
    float mrun = -1e30f, lrun = 0.f;

    for (int jt = 0; jt < WTOK; jt += 16) {
        float s[16];
#pragma unroll
        for (int jj = 0; jj < 16; jj++) {
            const ull* kr = (const ull*)(Ks + (jt + jj) * 64);
            ull s2 = 0ull;
#pragma unroll
            for (int i = 0; i < 32; i++) ffma2(s2, q2[i], kr[i]);
            float2 sf = unpack2(s2);
            s[jj] = (sf.x + sf.y) * SCALE;
        }

        float mnew = mrun;
#pragma unroll
        for (int jj = 0; jj < 16; jj++) mnew = fmaxf(mnew, s[jj]);

        float corr = __expf(mrun - mnew);
        lrun *= corr;
        ull c2 = pack2(corr, corr);
#pragma unroll
        for (int i = 0; i < 32; i++) fmul2(acc2[i], c2);

#pragma unroll
        for (int jj = 0; jj < 16; jj++) {
            float p = __expf(s[jj] - mnew);
            lrun += p;
            ull p2 = pack2(p, p);
            const ull* vr = (const ull*)(Vs + (jt + jj) * 64);
#pragma unroll
            for (int i = 0; i < 32; i++) ffma2(acc2[i], p2, vr[i]);
        }
        mrun = mnew;
    }

    float inv = 1.f / lrun;
    int n = perm_tok(wnd * WTOK + tid);   // original token position (inverse perm)
    size_t rowoff = ((size_t)(b * NTOK + n)) * CCH + h * HDIM;
    __nv_bfloat162* yh2 = (__nv_bfloat162*)(g_yh + rowoff);
    __nv_bfloat162* yl2 = (__nv_bfloat162*)(g_yl + rowoff);
#pragma unroll
    for (int i = 0; i < 32; i++) {
        float2 a = unpack2(acc2[i]);
        float vx = a.x * inv, vy = a.y * inv;
        __nv_bfloat16 hx = __float2bfloat16(vx), hy = __float2bfloat16(vy);
        __nv_bfloat162 hv; hv.x = hx; hv.y = hy;
        yh2[i] = hv;
        __nv_bfloat162 lv;
        lv.x = __float2bfloat16(vx - __bfloat162float(hx));
        lv.y = __float2bfloat16(vy - __bfloat162float(hy));
        yl2[i] = lv;
    }
}

// ---------------- launch ----------------
extern "C" void kernel_launch(void* const* d_in, const int* in_sizes, int n_in,
                              void* d_out, int out_size)
{
    const float* x      = (const float*)d_in[0];
    const float* qkv_w  = (const float*)d_in[1];
    const float* proj_w = (const float*)d_in[2];
    const float* proj_b = (const float*)d_in[3];
    float* out = (float*)d_out;

    cudaFuncSetAttribute(attn_kernel, cudaFuncAttributeMaxDynamicSharedMemorySize, 196608);
    cudaFuncSetAttribute(gemm_mma<0>, cudaFuncAttributeMaxDynamicSharedMemorySize, GM_SMEM);
    cudaFuncSetAttribute(gemm_mma<1>, cudaFuncAttributeMaxDynamicSharedMemorySize, GM_SMEM);

    convert_x<<<MTOT, 192>>>(x);
    convert_w<<<3072, 192>>>(qkv_w, proj_w);

    // QKV: M=32768 x N=2304 -> (18, 256)
    gemm_mma<0><<<dim3(18, 256), 256, GM_SMEM>>>(nullptr, nullptr);

    attn_kernel<<<BATCH * NWIN * NHEAD, 256, 196608>>>();

    // proj: M=32768 x N=768 -> (6, 256)
    gemm_mma<1><<<dim3(6, 256), 256, GM_SMEM>>>(proj_b, out);
}

// round 9
// speedup vs baseline: 3.8537x; 1.3028x over previous
#include <cuda_runtime.h>
#include <cuda_bf16.h>

// ---------------- problem constants ----------------
#define BATCH 8
#define NTOK  4096
#define CCH   768
#define NHEAD 12
#define HDIM  64
#define NWIN  16
#define WTOK  256
#define K_DIM 768
#define SCALE 0.125f
#define MTOT  (BATCH * NTOK)     // 32768

typedef unsigned long long ull;
typedef unsigned int u32;

// ---------------- device scratch ----------------
// QKV as bf16 hi/lo planes, [t][b][w][h][r][d]
__device__ __nv_bfloat16 g_qkvh[3u * BATCH * NWIN * NHEAD * WTOK * HDIM];
__device__ __nv_bfloat16 g_qkvl[3u * BATCH * NWIN * NHEAD * WTOK * HDIM];
__device__ __nv_bfloat16 g_xh[(size_t)MTOT * K_DIM];
__device__ __nv_bfloat16 g_xl[(size_t)MTOT * K_DIM];
__device__ __nv_bfloat16 g_yh[(size_t)MTOT * K_DIM];
__device__ __nv_bfloat16 g_yl[(size_t)MTOT * K_DIM];
__device__ __nv_bfloat16 g_wqh[2304 * 768], g_wql[2304 * 768];
__device__ __nv_bfloat16 g_wph[768 * 768],  g_wpl[768 * 768];

// ---------------- helpers ----------------
__device__ __forceinline__ int perm_tok(int p) {
    int wnd = p >> 8, r = p & 255;
    int wr = wnd >> 2, wc = wnd & 3;
    int i = r >> 4, j = r & 15;
    return ((wr << 4) + i) * 64 + (wc << 4) + j;
}
__device__ __forceinline__ u32 smem_u32(const void* p) {
    u32 a;
    asm("{ .reg .u64 t; cvta.to.shared.u64 t, %1; cvt.u32.u64 %0, t; }" : "=r"(a) : "l"(p));
    return a;
}
__device__ __forceinline__ void ldsm4(u32& r0, u32& r1, u32& r2, u32& r3, u32 addr) {
    asm volatile("ldmatrix.sync.aligned.m8n8.x4.shared.b16 {%0,%1,%2,%3}, [%4];"
                 : "=r"(r0), "=r"(r1), "=r"(r2), "=r"(r3) : "r"(addr));
}
__device__ __forceinline__ void ldsm4t(u32& r0, u32& r1, u32& r2, u32& r3, u32 addr) {
    asm volatile("ldmatrix.sync.aligned.m8n8.x4.trans.shared.b16 {%0,%1,%2,%3}, [%4];"
                 : "=r"(r0), "=r"(r1), "=r"(r2), "=r"(r3) : "r"(addr));
}
__device__ __forceinline__ void mma16816(float* c, const u32* a, const u32* b) {
    asm volatile("mma.sync.aligned.m16n8k16.row.col.f32.bf16.bf16.f32 "
                 "{%0,%1,%2,%3}, {%4,%5,%6,%7}, {%8,%9}, {%0,%1,%2,%3};"
                 : "+f"(c[0]), "+f"(c[1]), "+f"(c[2]), "+f"(c[3])
                 : "r"(a[0]), "r"(a[1]), "r"(a[2]), "r"(a[3]), "r"(b[0]), "r"(b[1]));
}
__device__ __forceinline__ void cpasync16(u32 saddr, const void* g) {
    asm volatile("cp.async.cg.shared.global [%0], [%1], 16;" :: "r"(saddr), "l"(g) : "memory");
}
#define CP_COMMIT()  asm volatile("cp.async.commit_group;" ::: "memory")
#define CP_WAIT(n)   asm volatile("cp.async.wait_group %0;" :: "n"(n) : "memory")

// pack two f32 -> bf16x2 (element0 = x0)
__device__ __forceinline__ u32 pkbf2(float x0, float x1) {
    u32 r;
    asm("cvt.rn.bf16x2.f32 %0, %2, %1;" : "=r"(r) : "f"(x0), "f"(x1));
    return r;
}

// ---------------- convert kernels ----------------
__global__ __launch_bounds__(192) void convert_x(const float* __restrict__ x)
{
    const int m = blockIdx.x;
    const int t = threadIdx.x;
    const int b = m >> 12, p = m & 4095;
    const float4* src = (const float4*)(x + (size_t)((b << 12) + perm_tok(p)) * K_DIM);
    float4 v = src[t];
    __nv_bfloat16 h0 = __float2bfloat16(v.x), h1 = __float2bfloat16(v.y);
    __nv_bfloat16 h2 = __float2bfloat16(v.z), h3 = __float2bfloat16(v.w);
    __nv_bfloat162* dh = (__nv_bfloat162*)(g_xh + (size_t)m * K_DIM);
    __nv_bfloat162* dl = (__nv_bfloat162*)(g_xl + (size_t)m * K_DIM);
    __nv_bfloat162 a; a.x = h0; a.y = h1; dh[t * 2] = a;
    a.x = h2; a.y = h3; dh[t * 2 + 1] = a;
    a.x = __float2bfloat16(v.x - __bfloat162float(h0));
    a.y = __float2bfloat16(v.y - __bfloat162float(h1));
    dl[t * 2] = a;
    a.x = __float2bfloat16(v.z - __bfloat162float(h2));
    a.y = __float2bfloat16(v.w - __bfloat162float(h3));
    dl[t * 2 + 1] = a;
}

__global__ __launch_bounds__(192) void convert_w(const float* __restrict__ qkv_w,
                                                 const float* __restrict__ proj_w)
{
    const int row = blockIdx.x;
    const int t = threadIdx.x;
    const float* src;
    __nv_bfloat16 *dh, *dl;
    if (row < 2304) {
        src = qkv_w + (size_t)row * 768;
        dh = g_wqh + (size_t)row * 768; dl = g_wql + (size_t)row * 768;
    } else {
        int r2 = row - 2304;
        src = proj_w + (size_t)r2 * 768;
        dh = g_wph + (size_t)r2 * 768; dl = g_wpl + (size_t)r2 * 768;
    }
    float4 v = ((const float4*)src)[t];
    __nv_bfloat16 h0 = __float2bfloat16(v.x), h1 = __float2bfloat16(v.y);
    __nv_bfloat16 h2 = __float2bfloat16(v.z), h3 = __float2bfloat16(v.w);
    __nv_bfloat162 a;
    a.x = h0; a.y = h1; ((__nv_bfloat162*)dh)[t * 2] = a;
    a.x = h2; a.y = h3; ((__nv_bfloat162*)dh)[t * 2 + 1] = a;
    a.x = __float2bfloat16(v.x - __bfloat162float(h0));
    a.y = __float2bfloat16(v.y - __bfloat162float(h1));
    ((__nv_bfloat162*)dl)[t * 2] = a;
    a.x = __float2bfloat16(v.z - __bfloat162float(h2));
    a.y = __float2bfloat16(v.w - __bfloat162float(h3));
    ((__nv_bfloat162*)dl)[t * 2 + 1] = a;
}

// ---------------- mma.sync bf16 3-term-split GEMM ----------------
// C[m][n] = sum_k A[m][k]*W[n][k];  C = Ah*Wh + Ah*Wl + Al*Wh  (fp32 accum)
// CTA 128x128, BK=32, 8 warps (4x2), warp tile 32x64, double-buffered cp.async.
#define GM_SMEM 81920

template <int MODE>
__global__ __launch_bounds__(256, 1)
void gemm_mma(const float* __restrict__ bias, float* __restrict__ Cout)
{
    extern __shared__ char smem[];
    const __nv_bfloat16* Abase_h = (MODE == 0) ? g_xh : g_yh;
    const __nv_bfloat16* Abase_l = (MODE == 0) ? g_xl : g_yl;
    const __nv_bfloat16* Wbase_h = (MODE == 0) ? g_wqh : g_wph;
    const __nv_bfloat16* Wbase_l = (MODE == 0) ? g_wql : g_wpl;

    const int tid = threadIdx.x;
    const int lane = tid & 31, wid = tid >> 5;
    const int wy = wid >> 1, wx = wid & 1;
    const int m0 = blockIdx.y * 128;
    const int n0 = blockIdx.x * 128;
    const u32 sb = smem_u32(smem);

    const __nv_bfloat16* Ahp = Abase_h + (size_t)m0 * 768;
    const __nv_bfloat16* Alp = Abase_l + (size_t)m0 * 768;
    const __nv_bfloat16* Whp = Wbase_h + (size_t)n0 * 768;
    const __nv_bfloat16* Wlp = Wbase_l + (size_t)n0 * 768;

    float acc[2][8][4];
#pragma unroll
    for (int mt = 0; mt < 2; mt++)
#pragma unroll
        for (int nt = 0; nt < 8; nt++)
#pragma unroll
            for (int j = 0; j < 4; j++) acc[mt][nt][j] = 0.f;

    const u32 aOff = (u32)((wy * 32 + (lane & 15)) * 80 + ((lane >> 4) * 16));
    const u32 bOff = (u32)((wx * 64 + ((lane >> 4) << 3) + (lane & 7)) * 80
                           + (((lane >> 3) & 1) * 16));

    const int s0 = tid, row0 = s0 >> 2, q0 = s0 & 3;
    const int s1 = tid + 256, row1 = s1 >> 2, q1 = s1 & 3;

#define LOAD_TILE(c, buf) do {                                                    \
    u32 dbase = sb + (u32)(buf) * 40960u;                                         \
    int kk = (c) * 32;                                                            \
    cpasync16(dbase +         (u32)(row0 * 80 + q0 * 16), Ahp + (size_t)row0 * 768 + kk + q0 * 8); \
    cpasync16(dbase +         (u32)(row1 * 80 + q1 * 16), Ahp + (size_t)row1 * 768 + kk + q1 * 8); \
    cpasync16(dbase + 10240 + (u32)(row0 * 80 + q0 * 16), Alp + (size_t)row0 * 768 + kk + q0 * 8); \
    cpasync16(dbase + 10240 + (u32)(row1 * 80 + q1 * 16), Alp + (size_t)row1 * 768 + kk + q1 * 8); \
    cpasync16(dbase + 20480 + (u32)(row0 * 80 + q0 * 16), Whp + (size_t)row0 * 768 + kk + q0 * 8); \
    cpasync16(dbase + 20480 + (u32)(row1 * 80 + q1 * 16), Whp + (size_t)row1 * 768 + kk + q1 * 8); \
    cpasync16(dbase + 30720 + (u32)(row0 * 80 + q0 * 16), Wlp + (size_t)row0 * 768 + kk + q0 * 8); \
    cpasync16(dbase + 30720 + (u32)(row1 * 80 + q1 * 16), Wlp + (size_t)row1 * 768 + kk + q1 * 8); \
} while (0)

    LOAD_TILE(0, 0);
    CP_COMMIT();

    for (int c = 0; c < 24; c++) {
        const int buf = c & 1;
        if (c + 1 < 24) {
            LOAD_TILE(c + 1, buf ^ 1);
            CP_COMMIT();
            CP_WAIT(1);
        } else {
            CP_WAIT(0);
        }
        __syncthreads();

        const u32 base = sb + (u32)buf * 40960u;
#pragma unroll
        for (int ks = 0; ks < 2; ks++) {
            const u32 kb = (u32)(ks * 32);
            u32 ah[2][4], al[2][4], bh[8][2], bl[8][2];
#pragma unroll
            for (int mt = 0; mt < 2; mt++) {
                u32 ad = base + aOff + (u32)(mt * 16 * 80) + kb;
                ldsm4(ah[mt][0], ah[mt][1], ah[mt][2], ah[mt][3], ad);
                ldsm4(al[mt][0], al[mt][1], al[mt][2], al[mt][3], ad + 10240);
            }
#pragma unroll
            for (int p = 0; p < 4; p++) {
                u32 bd = base + 20480 + bOff + (u32)(p * 16 * 80) + kb;
                u32 r0, r1, r2, r3;
                ldsm4(r0, r1, r2, r3, bd);
                bh[2 * p][0] = r0; bh[2 * p][1] = r1;
                bh[2 * p + 1][0] = r2; bh[2 * p + 1][1] = r3;
                ldsm4(r0, r1, r2, r3, bd + 10240);
                bl[2 * p][0] = r0; bl[2 * p][1] = r1;
                bl[2 * p + 1][0] = r2; bl[2 * p + 1][1] = r3;
            }
#pragma unroll
            for (int mt = 0; mt < 2; mt++)
#pragma unroll
                for (int nt = 0; nt < 8; nt++) {
                    mma16816(acc[mt][nt], ah[mt], bh[nt]);
                    mma16816(acc[mt][nt], ah[mt], bl[nt]);
                    mma16816(acc[mt][nt], al[mt], bh[nt]);
                }
        }
        __syncthreads();
    }

    // ---- epilogue ----
#pragma unroll
    for (int mt = 0; mt < 2; mt++) {
        const int m_g = m0 + wy * 32 + mt * 16 + (lane >> 2);
        if (MODE == 0) {
            const int bq = m_g >> 12, ptok = m_g & 4095;
            const int wnd = ptok >> 8, rr = ptok & 255;
#pragma unroll
            for (int nt = 0; nt < 8; nt++) {
                const int ncol = n0 + wx * 64 + nt * 8;
                const int t = ncol / 768;
                const int rem = ncol - t * 768;
                const int h = rem >> 6;
                const int d = (rem & 63) + 2 * (lane & 3);
                size_t rowbase = ((((size_t)t * 8 + bq) * 16 + wnd) * 12 + h) * 256;
                // hi/lo bf16 pairs
                float v0 = acc[mt][nt][0], v1 = acc[mt][nt][1];
                float v2 = acc[mt][nt][2], v3 = acc[mt][nt][3];
                __nv_bfloat16 h0 = __float2bfloat16(v0), h1 = __float2bfloat16(v1);
                __nv_bfloat16 h2 = __float2bfloat16(v2), h3 = __float2bfloat16(v3);
                *(u32*)&g_qkvh[(rowbase + rr) * 64 + d] =
                    pkbf2(__bfloat162float(h0), __bfloat162float(h1));
                *(u32*)&g_qkvl[(rowbase + rr) * 64 + d] =
                    pkbf2(v0 - __bfloat162float(h0), v1 - __bfloat162float(h1));
                *(u32*)&g_qkvh[(rowbase + rr + 8) * 64 + d] =
                    pkbf2(__bfloat162float(h2), __bfloat162float(h3));
                *(u32*)&g_qkvl[(rowbase + rr + 8) * 64 + d] =
                    pkbf2(v2 - __bfloat162float(h2), v3 - __bfloat162float(h3));
            }
        } else {
#pragma unroll
            for (int nt = 0; nt < 8; nt++) {
                const int ncol = n0 + wx * 64 + nt * 8 + 2 * (lane & 3);
                const float b0 = bias[ncol], b1 = bias[ncol + 1];
                *(float2*)(Cout + (size_t)m_g * 768 + ncol) =
                    make_float2(acc[mt][nt][0] + b0, acc[mt][nt][1] + b1);
                *(float2*)(Cout + (size_t)(m_g + 8) * 768 + ncol) =
                    make_float2(acc[mt][nt][2] + b0, acc[mt][nt][3] + b1);
            }
        }
    }
#undef LOAD_TILE
}

// ---------------- flash attention on mma.sync, 3-term bf16 split ----------------
// one block per (b, window, head); 8 warps x 32 query rows; key chunks of 64.
// smem: 6 planes (Qh,Ql,Kh,Kl,Vh,Vl), 256 rows x 72 halves (144B stride) = 36864B each.
#define AT_PL   36864
#define AT_SMEM (6 * AT_PL)      // 221184

__global__ __launch_bounds__(256, 1)
void attn_mma()
{
    extern __shared__ char smem[];
    const u32 sb = smem_u32(smem);

    const int tid = threadIdx.x;
    const int lane = tid & 31, wid = tid >> 5;
    const int blk = blockIdx.x;
    const int h = blk % NHEAD;
    const int t2 = blk / NHEAD;
    const int wnd = t2 % NWIN;
    const int b = t2 / NWIN;

    // ---- load 6 planes into padded smem ----
    {
        const size_t blkoff = (((size_t)b * NWIN + wnd) * NHEAD + h) * (WTOK * HDIM);
        const size_t plane_sz = (size_t)BATCH * NWIN * NHEAD * WTOK * HDIM;
#pragma unroll
        for (int p6 = 0; p6 < 6; p6++) {
            const int t = p6 >> 1;
            const __nv_bfloat16* src = ((p6 & 1) ? g_qkvl : g_qkvh) + (size_t)t * plane_sz + blkoff;
            const u32 dpl = sb + (u32)p6 * AT_PL;
#pragma unroll
            for (int i = 0; i < 8; i++) {
                int seg = i * 256 + tid;          // 0..2047
                int row = seg >> 3, sc = seg & 7;
                uint4 v = ((const uint4*)(src + row * 64))[sc];
                *(uint4*)(smem + (size_t)p6 * AT_PL + row * 144 + sc * 16) = v;
            }
        }
    }
    __syncthreads();

    float out[2][8][4];
#pragma unroll
    for (int mt = 0; mt < 2; mt++)
#pragma unroll
        for (int nt = 0; nt < 8; nt++)
#pragma unroll
            for (int j = 0; j < 4; j++) out[mt][nt][j] = 0.f;
    float mrun[2][2] = {{-1e30f, -1e30f}, {-1e30f, -1e30f}};
    float lrun[2][2] = {{0.f, 0.f}, {0.f, 0.f}};

    const u32 qrow_base = (u32)(wid * 32 + (lane & 15));
    const u32 qcol = (u32)((lane >> 4) * 16);
    const u32 krow_off = (u32)(((lane >> 4) << 3) + (lane & 7));
    const u32 kcol = (u32)(((lane >> 3) & 1) * 16);
    const u32 vrow_off = (u32)(lane & 15);
    const u32 vcol = (u32)((lane >> 4) * 16);

    for (int jc = 0; jc < 4; jc++) {
        // ---- S = scale * (Qh*Kh' + Qh*Kl' + Ql*Kh') ----
        float s[2][8][4];
#pragma unroll
        for (int mt = 0; mt < 2; mt++)
#pragma unroll
            for (int nt = 0; nt < 8; nt++)
#pragma unroll
                for (int j = 0; j < 4; j++) s[mt][nt][j] = 0.f;

#pragma unroll
        for (int ks = 0; ks < 4; ks++) {
            u32 qh[2][4], ql[2][4];
#pragma unroll
            for (int mt = 0; mt < 2; mt++) {
                u32 ad = sb + (qrow_base + mt * 16) * 144 + qcol + ks * 32;
                ldsm4(qh[mt][0], qh[mt][1], qh[mt][2], qh[mt][3], ad);
                ldsm4(ql[mt][0], ql[mt][1], ql[mt][2], ql[mt][3], ad + AT_PL);
            }
            u32 kh[8][2], kl[8][2];
#pragma unroll
            for (int p = 0; p < 4; p++) {
                u32 row = (u32)(jc * 64 + p * 16) + krow_off;
                u32 bd = sb + 2 * AT_PL + row * 144 + kcol + ks * 32;
                u32 r0, r1, r2, r3;
                ldsm4(r0, r1, r2, r3, bd);
                kh[2 * p][0] = r0; kh[2 * p][1] = r1;
                kh[2 * p + 1][0] = r2; kh[2 * p + 1][1] = r3;
                ldsm4(r0, r1, r2, r3, bd + AT_PL);
                kl[2 * p][0] = r0; kl[2 * p][1] = r1;
                kl[2 * p + 1][0] = r2; kl[2 * p + 1][1] = r3;
            }
#pragma unroll
            for (int mt = 0; mt < 2; mt++)
#pragma unroll
                for (int nt = 0; nt < 8; nt++) {
                    mma16816(s[mt][nt], qh[mt], kh[nt]);
                    mma16816(s[mt][nt], qh[mt], kl[nt]);
                    mma16816(s[mt][nt], ql[mt], kh[nt]);
                }
        }
#pragma unroll
        for (int mt = 0; mt < 2; mt++)
#pragma unroll
            for (int nt = 0; nt < 8; nt++)
#pragma unroll
                for (int j = 0; j < 4; j++) s[mt][nt][j] *= SCALE;

        // ---- online softmax ----
#pragma unroll
        for (int mt = 0; mt < 2; mt++) {
            float mx0 = -1e30f, mx1 = -1e30f;
#pragma unroll
            for (int nt = 0; nt < 8; nt++) {
                mx0 = fmaxf(mx0, fmaxf(s[mt][nt][0], s[mt][nt][1]));
                mx1 = fmaxf(mx1, fmaxf(s[mt][nt][2], s[mt][nt][3]));
            }
            mx0 = fmaxf(mx0, __shfl_xor_sync(0xffffffffu, mx0, 1));
            mx0 = fmaxf(mx0, __shfl_xor_sync(0xffffffffu, mx0, 2));
            mx1 = fmaxf(mx1, __shfl_xor_sync(0xffffffffu, mx1, 1));
            mx1 = fmaxf(mx1, __shfl_xor_sync(0xffffffffu, mx1, 2));
            const float mn0 = fmaxf(mrun[mt][0], mx0);
            const float mn1 = fmaxf(mrun[mt][1], mx1);
            const float c0 = __expf(mrun[mt][0] - mn0);
            const float c1 = __expf(mrun[mt][1] - mn1);
            mrun[mt][0] = mn0; mrun[mt][1] = mn1;
            lrun[mt][0] *= c0; lrun[mt][1] *= c1;
#pragma unroll
            for (int nt = 0; nt < 8; nt++) {
                out[mt][nt][0] *= c0; out[mt][nt][1] *= c0;
                out[mt][nt][2] *= c1; out[mt][nt][3] *= c1;
            }
            float sum0 = 0.f, sum1 = 0.f;
#pragma unroll
            for (int nt = 0; nt < 8; nt++) {
                float p0 = __expf(s[mt][nt][0] - mn0);
                float p1 = __expf(s[mt][nt][1] - mn0);
                float p2 = __expf(s[mt][nt][2] - mn1);
                float p3 = __expf(s[mt][nt][3] - mn1);
                s[mt][nt][0] = p0; s[mt][nt][1] = p1;
                s[mt][nt][2] = p2; s[mt][nt][3] = p3;
                sum0 += p0 + p1; sum1 += p2 + p3;
            }
            sum0 += __shfl_xor_sync(0xffffffffu, sum0, 1);
            sum0 += __shfl_xor_sync(0xffffffffu, sum0, 2);
            sum1 += __shfl_xor_sync(0xffffffffu, sum1, 1);
            sum1 += __shfl_xor_sync(0xffffffffu, sum1, 2);
            lrun[mt][0] += sum0; lrun[mt][1] += sum1;
        }

        // ---- O += (Ph*Vh + Ph*Vl + Pl*Vh) ----
#pragma unroll
        for (int ks = 0; ks < 4; ks++) {
            u32 pah[2][4], pal[2][4];
#pragma unroll
            for (int mt = 0; mt < 2; mt++) {
#pragma unroll
                for (int half = 0; half < 2; half++) {
                    const float* sv = s[mt][2 * ks + half];
                    float h0f = __bfloat162float(__float2bfloat16(sv[0]));
                    float h1f = __bfloat162float(__float2bfloat16(sv[1]));
                    float h2f = __bfloat162float(__float2bfloat16(sv[2]));
                    float h3f = __bfloat162float(__float2bfloat16(sv[3]));
                    pah[mt][0 + 2 * half] = pkbf2(h0f, h1f);
                    pah[mt][1 + 2 * half] = pkbf2(h2f, h3f);
                    pal[mt][0 + 2 * half] = pkbf2(sv[0] - h0f, sv[1] - h1f);
                    pal[mt][1 + 2 * half] = pkbf2(sv[2] - h2f, sv[3] - h3f);
                }
            }
            u32 vh[8][2], vl[8][2];
#pragma unroll
            for (int p = 0; p < 4; p++) {
                u32 row = (u32)(jc * 64 + ks * 16) + vrow_off;
                u32 vd = sb + 4 * AT_PL + row * 144 + vcol + p * 32;
                u32 r0, r1, r2, r3;
                ldsm4t(r0, r1, r2, r3, vd);
                vh[2 * p][0] = r0; vh[2 * p][1] = r1;
                vh[2 * p + 1][0] = r2; vh[2 * p + 1][1] = r3;
                ldsm4t(r0, r1, r2, r3, vd + AT_PL);
                vl[2 * p][0] = r0; vl[2 * p][1] = r1;
                vl[2 * p + 1][0] = r2; vl[2 * p + 1][1] = r3;
            }
#pragma unroll
            for (int mt = 0; mt < 2; mt++)
#pragma unroll
                for (int nt = 0; nt < 8; nt++) {
                    mma16816(out[mt][nt], pah[mt], vh[nt]);
                    mma16816(out[mt][nt], pah[mt], vl[nt]);
                    mma16816(out[mt][nt], pal[mt], vh[nt]);
                }
        }
    }

    // ---- epilogue: scale by 1/l, inverse-perm scatter, write y hi/lo bf16 ----
#pragma unroll
    for (int mt = 0; mt < 2; mt++) {
        const float inv0 = 1.f / lrun[mt][0];
        const float inv1 = 1.f / lrun[mt][1];
#pragma unroll
        for (int half = 0; half < 2; half++) {
            const int row = wid * 32 + mt * 16 + (lane >> 2) + half * 8;
            const int n = perm_tok(wnd * WTOK + row);
            const size_t base = ((size_t)(b * NTOK + n)) * CCH + h * HDIM;
            const float inv = half ? inv1 : inv0;
#pragma unroll
            for (int nt = 0; nt < 8; nt++) {
                const int col = nt * 8 + 2 * (lane & 3);
                float v0 = out[mt][nt][2 * half] * inv;
                float v1 = out[mt][nt][2 * half + 1] * inv;
                float h0f = __bfloat162float(__float2bfloat16(v0));
                float h1f = __bfloat162float(__float2bfloat16(v1));
                *(u32*)&g_yh[base + col] = pkbf2(h0f, h1f);
                *(u32*)&g_yl[base + col] = pkbf2(v0 - h0f, v1 - h1f);
            }
        }
    }
}

// ---------------- launch ----------------
extern "C" void kernel_launch(void* const* d_in, const int* in_sizes, int n_in,
                              void* d_out, int out_size)
{
    const float* x      = (const float*)d_in[0];
    const float* qkv_w  = (const float*)d_in[1];
    const float* proj_w = (const float*)d_in[2];
    const float* proj_b = (const float*)d_in[3];
    float* out = (float*)d_out;

    cudaFuncSetAttribute(attn_mma, cudaFuncAttributeMaxDynamicSharedMemorySize, AT_SMEM);
    cudaFuncSetAttribute(gemm_mma<0>, cudaFuncAttributeMaxDynamicSharedMemorySize, GM_SMEM);
    cudaFuncSetAttribute(gemm_mma<1>, cudaFuncAttributeMaxDynamicSharedMemorySize, GM_SMEM);

    convert_x<<<MTOT, 192>>>(x);
    convert_w<<<3072, 192>>>(qkv_w, proj_w);

    // QKV: M=32768 x N=2304 -> (18, 256)
    gemm_mma<0><<<dim3(18, 256), 256, GM_SMEM>>>(nullptr, nullptr);

    attn_mma<<<BATCH * NWIN * NHEAD, 256, AT_SMEM>>>();

    // proj: M=32768 x N=768 -> (6, 256)
    gemm_mma<1><<<dim3(6, 256), 256, GM_SMEM>>>(proj_b, out);
}